// round 15
// baseline (speedup 1.0000x reference)
#include <cuda_runtime.h>
#include <cuda_bf16.h>
#include <cuda_fp16.h>
#include <math.h>
#include <stdint.h>

// Problem constants (fixed by reference setup_inputs)
#define BATCH   2
#define NSEQ    2048
#define DMODEL  1024
#define NHEADS  16
#define DHEAD   64
#define INNER   (NHEADS * DHEAD)       // 1024
#define QKV_N   (3 * INNER)            // 3072
#define WIN     16
#define ATT_SCALE 0.125f
#define MTOT    (BATCH * NSEQ)         // 4096

// ---------------------------------------------------------------------------
// Scratch (device globals: allocation-free rule)
// ---------------------------------------------------------------------------
__device__ float g_qkv[MTOT * QKV_N];                   // [4096, 3072]
__device__ __half g_a_hi[MTOT * DMODEL];                // act fp16 (x, then attn out)
__device__ __half g_wq_hi[QKV_N * DMODEL];              // W_qkv^T fp16 [3072,1024]
__device__ __half g_wo_hi[DMODEL * INNER];              // W_out^T fp16 [1024,1024]

// ---------------------------------------------------------------------------
// PTX helpers (no arch-feature-suffixed instructions: plain compute_103 OK)
// ---------------------------------------------------------------------------
__device__ __forceinline__ uint32_t smem_u32(const void* p) {
    uint32_t a;
    asm("{ .reg .u64 t; cvta.to.shared.u64 t, %1; cvt.u32.u64 %0, t; }"
        : "=r"(a) : "l"(p));
    return a;
}
__device__ __forceinline__ void cp_async16(uint32_t saddr, const void* gaddr) {
    asm volatile("cp.async.cg.shared.global [%0], [%1], 16;"
                 :: "r"(saddr), "l"(gaddr) : "memory");
}
#define CP_COMMIT() asm volatile("cp.async.commit_group;" ::: "memory")
#define CP_WAIT(n)  asm volatile("cp.async.wait_group %0;" :: "n"(n) : "memory")

__device__ __forceinline__ void ldm_x4(uint32_t* r, uint32_t addr) {
    asm volatile("ldmatrix.sync.aligned.m8n8.x4.shared.b16 {%0,%1,%2,%3}, [%4];"
                 : "=r"(r[0]), "=r"(r[1]), "=r"(r[2]), "=r"(r[3]) : "r"(addr));
}
__device__ __forceinline__ void mma_f16(float* d, const uint32_t* a,
                                        const uint32_t* b) {
    asm volatile(
        "mma.sync.aligned.m16n8k16.row.col.f32.f16.f16.f32 "
        "{%0,%1,%2,%3}, {%4,%5,%6,%7}, {%8,%9}, {%0,%1,%2,%3};"
        : "+f"(d[0]), "+f"(d[1]), "+f"(d[2]), "+f"(d[3])
        : "r"(a[0]), "r"(a[1]), "r"(a[2]), "r"(a[3]), "r"(b[0]), "r"(b[1]));
}

// XOR-swizzled smem layout: 64B rows, 4x16B chunks, chunk ^= (row>>1)&3.
// Conflict-free for BOTH cp.async 16B stores and ldmatrix 8-row phases.
__device__ __forceinline__ uint32_t swz(int row, int chunk) {
    return (uint32_t)(row * 64 + ((chunk ^ ((row >> 1) & 3)) << 4));
}

// ---------------------------------------------------------------------------
// Plain fp16 tensor-core GEMM (mma.sync), single K pass:
//   C[M,N] = A@B^T  (+ bias)
// A fp16 [M,K] row-major; B fp16 [N,K] row-major (weights pre-transposed).
// CTA 128x256, BK=32, 8 warps (2M x 4N => warp tile 64x64), swizzled smem,
// 4-stage cp.async, lookahead 3; per stage: CP_WAIT -> barrier -> issue.
// 1 CTA/SM (reg-limited). Requires M%128==0, N%256==0, K%32==0, K>=96.
// ---------------------------------------------------------------------------
#define TILE_A  (128 * 64)              // 8192 B  (A tile, 64B rows)
#define TILE_BB (256 * 64)              // 16384 B (B tile, 64B rows)
#define STAGE_B (TILE_A + TILE_BB)      // 24576 B per stage
#define NSTAGE  4
#define GSM_BYTES (NSTAGE * STAGE_B)    // 98304

__global__ __launch_bounds__(256, 1)
void gemm_fp16(const __half* __restrict__ A,
               const __half* __restrict__ B,
               const float* __restrict__ bias,
               float* __restrict__ C,
               int M, int N, int K)
{
    constexpr int L = NSTAGE - 1;       // lookahead groups (3)

    extern __shared__ char smem[];
    const uint32_t sbase = smem_u32(smem);

    const int tid    = threadIdx.x;
    const int wid    = tid >> 5;
    const int lane   = tid & 31;
    const int warp_m = wid >> 2;        // 0..1  (64 rows)
    const int warp_n = wid & 3;         // 0..3  (64 cols)
    const int bm     = blockIdx.y * 128;
    const int bn     = blockIdx.x * 256;

    const int T = K >> 5;               // BK=32 k-tiles

    const int ld_row0 = tid >> 2;              // 0..63
    const int ld_ch   = tid & 3;               // 16B chunk 0..3
    const int a_row_l = (lane & 15);
    const int a_ch_l  = lane >> 4;             // 0..1
    const int b_row_l = ((lane >> 4) << 3) + (lane & 7);
    const int b_ch_l  = (lane >> 3) & 1;

    float acc[4][8][4];
    #pragma unroll
    for (int i = 0; i < 4; i++)
        #pragma unroll
        for (int j = 0; j < 8; j++)
            #pragma unroll
            for (int q = 0; q < 4; q++) acc[i][j][q] = 0.f;

    auto issue = [&](int s) {
        const int kc = s * 32;
        const uint32_t st = sbase + (s % NSTAGE) * STAGE_B;
        // A tile: 128 rows, 2 chunks/thread
        #pragma unroll
        for (int i = 0; i < 2; i++) {
            const int row = ld_row0 + i * 64;
            cp_async16(st + swz(row, ld_ch),
                       A + (size_t)(bm + row) * K + kc + ld_ch * 8);
        }
        // B tile: 256 rows, 4 chunks/thread
        #pragma unroll
        for (int i = 0; i < 4; i++) {
            const int row = ld_row0 + i * 64;
            cp_async16(st + TILE_A + swz(row, ld_ch),
                       B + (size_t)(bn + row) * K + kc + ld_ch * 8);
        }
        CP_COMMIT();
    };

    #pragma unroll
    for (int i = 0; i < L; i++) issue(i);      // K >= 96 => T >= L

    for (int s = 0; s < T; ++s) {
        // 1) Complete own group s, keeping up to L-1 groups in flight
        if (s + 2 < T)      { CP_WAIT(2); }
        else if (s + 1 < T) { CP_WAIT(1); }
        else                { CP_WAIT(0); }
        // 2) Publish group s across all threads
        __syncthreads();
        // 3) Refill buffer (s-1)%NSTAGE (fully consumed before this barrier)
        if (s + L < T) issue(s + L);

        const uint32_t stA = sbase + (s % NSTAGE) * STAGE_B;
        const uint32_t stB = stA + TILE_A;

        #pragma unroll
        for (int kk = 0; kk < 2; ++kk) {
            uint32_t bf[4][4];
            #pragma unroll
            for (int nt = 0; nt < 4; ++nt) {
                const int row = warp_n * 64 + nt * 16 + b_row_l;
                ldm_x4(bf[nt], stB + swz(row, kk * 2 + b_ch_l));
            }
            #pragma unroll
            for (int mi = 0; mi < 4; ++mi) {
                uint32_t ah[4];
                const int row = warp_m * 64 + mi * 16 + a_row_l;
                ldm_x4(ah, stA + swz(row, kk * 2 + a_ch_l));
                #pragma unroll
                for (int nt = 0; nt < 4; ++nt) {
                    mma_f16(acc[mi][nt * 2 + 0], ah, &bf[nt][0]);
                    mma_f16(acc[mi][nt * 2 + 1], ah, &bf[nt][2]);
                }
            }
        }
    }

    // Epilogue
    const int tg = lane >> 2;
    const int tc = (lane & 3) * 2;
    #pragma unroll
    for (int mi = 0; mi < 4; ++mi) {
        const int r0 = bm + warp_m * 64 + mi * 16 + tg;
        #pragma unroll
        for (int ni = 0; ni < 8; ++ni) {
            const int c0 = bn + warp_n * 64 + ni * 8 + tc;
            float2 v0 = make_float2(acc[mi][ni][0], acc[mi][ni][1]);
            float2 v1 = make_float2(acc[mi][ni][2], acc[mi][ni][3]);
            if (bias) {
                const float bx = bias[c0], by = bias[c0 + 1];
                v0.x += bx; v0.y += by;
                v1.x += bx; v1.y += by;
            }
            *(float2*)(C + (size_t)r0 * N + c0)       = v0;
            *(float2*)(C + (size_t)(r0 + 8) * N + c0) = v1;
        }
    }
}

// ---------------------------------------------------------------------------
// fp32 -> fp16 (row-major, elementwise)
// ---------------------------------------------------------------------------
__global__ void split_hi_kernel(const float4* __restrict__ in,
                                uint2* __restrict__ hi, int n4)
{
    int i = blockIdx.x * blockDim.x + threadIdx.x;
    if (i >= n4) return;
    float4 v = in[i];
    union { __half h[4]; uint2 u; } H;
    #pragma unroll
    for (int j = 0; j < 4; ++j) H.h[j] = __float2half((&v.x)[j]);
    hi[i] = H.u;
}

// ---------------------------------------------------------------------------
// Transpose + convert: in fp32 [K,N] -> fp16 [N,K]
// ---------------------------------------------------------------------------
__global__ void tconv_kernel(const float* __restrict__ in,
                             __half* __restrict__ hi, int K, int N)
{
    __shared__ float t[32][33];
    const int tx = threadIdx.x & 31, ty = threadIdx.x >> 5;
    const int n0 = blockIdx.x * 32, k0 = blockIdx.y * 32;
    #pragma unroll
    for (int i = 0; i < 4; ++i)
        t[ty + i * 8][tx] = in[(size_t)(k0 + ty + i * 8) * N + n0 + tx];
    __syncthreads();
    #pragma unroll
    for (int i = 0; i < 4; ++i) {
        float v = t[tx][ty + i * 8];
        hi[(size_t)(n0 + ty + i * 8) * K + k0 + tx] = __float2half(v);
    }
}

// ---------------------------------------------------------------------------
// Windowed attention (top-k & padding masks are provable no-ops).
// Lane-per-key float4 scoring + lane-per-dim AV. Emits fp16 output.
// K/V rows padded to 68 floats: float4-aligned, conflict-free lane-per-key.
// ---------------------------------------------------------------------------
__global__ __launch_bounds__(256)
void attn_window_kernel(const float* __restrict__ qkv,
                        __half* __restrict__ ohi)
{
    __shared__ float qs[32][64];
    __shared__ float ks[64][68];
    __shared__ float vs[64][68];
    __shared__ float ps[8][4][34];

    const int qtile = blockIdx.x * 32;
    const int h     = blockIdx.y;
    const int bb    = blockIdx.z;
    const int tid   = threadIdx.x;

    const int kstart = qtile - WIN;
    const long base  = (long)bb * NSEQ * QKV_N;
    const int hoff   = h * DHEAD;

    #pragma unroll
    for (int idx = tid; idx < 32 * 16; idx += 256) {
        int r = idx >> 4, c = (idx & 15) << 2;
        *(float4*)(&qs[r][c]) =
            *(const float4*)(qkv + base + (long)(qtile + r) * QKV_N + hoff + c);
    }
    #pragma unroll
    for (int idx = tid; idx < 64 * 16; idx += 256) {
        int r = idx >> 4, c = (idx & 15) << 2;
        int jg = kstart + r;
        float4 kv = make_float4(0.f, 0.f, 0.f, 0.f);
        float4 vv = make_float4(0.f, 0.f, 0.f, 0.f);
        if (jg >= 0 && jg < NSEQ) {
            const float* rowp = qkv + base + (long)jg * QKV_N + hoff;
            kv = *(const float4*)(rowp + INNER + c);
            vv = *(const float4*)(rowp + 2 * INNER + c);
        }
        *(float4*)(&ks[r][c]) = kv;
        *(float4*)(&vs[r][c]) = vv;
    }
    __syncthreads();

    const int warp = tid >> 5;
    const int lane = tid & 31;

    #pragma unroll
    for (int q4 = 0; q4 < 4; ++q4) {
        const int qq = warp * 4 + q4;
        const int i  = qtile + qq;
        const int j0 = max(0, i - WIN);
        const int j1 = min(NSEQ - 1, i + WIN);
        const int W  = j1 - j0 + 1;
        const int rb  = j0 - kstart;
        const int jj  = rb + lane;
        const int jj2 = rb + 32;
        const bool v1 = (lane < W);
        const bool v2 = (W == 33);

        // float4 dot products (lane-per-key; q read is broadcast)
        float acc1 = 0.f, acc2 = 0.f;
        const float4* k1p = (const float4*)ks[jj];
        const float4* k2p = (const float4*)ks[jj2];
        const float4* qp  = (const float4*)qs[qq];
        #pragma unroll
        for (int d4 = 0; d4 < 16; ++d4) {
            const float4 qv = qp[d4];
            const float4 k1 = k1p[d4];
            const float4 k2 = k2p[d4];
            acc1 = fmaf(qv.x, k1.x, acc1); acc1 = fmaf(qv.y, k1.y, acc1);
            acc1 = fmaf(qv.z, k1.z, acc1); acc1 = fmaf(qv.w, k1.w, acc1);
            acc2 = fmaf(qv.x, k2.x, acc2); acc2 = fmaf(qv.y, k2.y, acc2);
            acc2 = fmaf(qv.z, k2.z, acc2); acc2 = fmaf(qv.w, k2.w, acc2);
        }
        float s1 = v1 ? acc1 * ATT_SCALE : -INFINITY;
        const float s2 = v2 ? acc2 * ATT_SCALE : -INFINITY;

        float m = s1;
        m = fmaxf(m, __shfl_xor_sync(0xffffffffu, m, 16));
        m = fmaxf(m, __shfl_xor_sync(0xffffffffu, m, 8));
        m = fmaxf(m, __shfl_xor_sync(0xffffffffu, m, 4));
        m = fmaxf(m, __shfl_xor_sync(0xffffffffu, m, 2));
        m = fmaxf(m, __shfl_xor_sync(0xffffffffu, m, 1));
        m = fmaxf(m, s2);

        const float e1 = __expf(s1 - m);
        const float e2 = __expf(s2 - m);
        float l = e1;
        l += __shfl_xor_sync(0xffffffffu, l, 16);
        l += __shfl_xor_sync(0xffffffffu, l, 8);
        l += __shfl_xor_sync(0xffffffffu, l, 4);
        l += __shfl_xor_sync(0xffffffffu, l, 2);
        l += __shfl_xor_sync(0xffffffffu, l, 1);
        l += e2;

        ps[warp][q4][lane] = e1;
        if (lane == 0) ps[warp][q4][32] = e2;
        __syncwarp();

        float a0 = 0.f, a1 = 0.f;
        #pragma unroll
        for (int j = 0; j < 33; ++j) {
            const float p = ps[warp][q4][j];
            a0 = fmaf(p, vs[rb + j][lane],      a0);
            a1 = fmaf(p, vs[rb + j][lane + 32], a1);
        }
        const float inv = 1.f / l;

        const long orow = ((long)(bb * NSEQ + i)) * INNER + hoff;
        ohi[orow + lane]      = __float2half(a0 * inv);
        ohi[orow + lane + 32] = __float2half(a1 * inv);
        __syncwarp();
    }
}

// ---------------------------------------------------------------------------
// kernel_launch
// ---------------------------------------------------------------------------
extern "C" void kernel_launch(void* const* d_in, const int* in_sizes, int n_in,
                              void* d_out, int out_size)
{
    const float* x    = (const float*)d_in[0];
    const float* Wqkv = (const float*)d_in[1];
    const float* Wout = (const float*)d_in[2];
    const float* bout = (const float*)d_in[3];
    float* out = (float*)d_out;

    float* qkv;
    __half *ahi, *wqh, *woh;
    cudaGetSymbolAddress((void**)&qkv, g_qkv);
    cudaGetSymbolAddress((void**)&ahi, g_a_hi);
    cudaGetSymbolAddress((void**)&wqh, g_wq_hi);
    cudaGetSymbolAddress((void**)&woh, g_wo_hi);

    static bool attr_set = false;
    if (!attr_set) {
        cudaFuncSetAttribute(gemm_fp16,
                             cudaFuncAttributeMaxDynamicSharedMemorySize, GSM_BYTES);
        attr_set = true;
    }

    // 1) conversions (x and weights, fp16)
    {
        int n4 = MTOT * DMODEL / 4;
        split_hi_kernel<<<(n4 + 255) / 256, 256>>>((const float4*)x,
                                                   (uint2*)ahi, n4);
        dim3 gq(QKV_N / 32, DMODEL / 32);
        tconv_kernel<<<gq, 256>>>(Wqkv, wqh, DMODEL, QKV_N);
        dim3 go(DMODEL / 32, INNER / 32);
        tconv_kernel<<<go, 256>>>(Wout, woh, INNER, DMODEL);
    }

    // 2) qkv = x @ W_qkv  (fp16, CTA 128x256)
    {
        dim3 grid(QKV_N / 256, MTOT / 128);
        gemm_fp16<<<grid, 256, GSM_BYTES>>>(ahi, wqh, nullptr, qkv,
                                            MTOT, QKV_N, DMODEL);
    }

    // 3) attention -> fp16 output into ahi
    {
        dim3 grid(NSEQ / 32, NHEADS, BATCH);
        attn_window_kernel<<<grid, 256>>>(qkv, ahi);
    }

    // 4) out = att @ W_out + b_out  (fp16, 128 CTAs)
    {
        dim3 grid(DMODEL / 256, MTOT / 128);
        gemm_fp16<<<grid, 256, GSM_BYTES>>>(ahi, woh, bout, out,
                                            MTOT, DMODEL, INNER);
    }
}

// round 16
// speedup vs baseline: 1.0709x; 1.0709x over previous
#include <cuda_runtime.h>
#include <cuda_bf16.h>
#include <cuda_fp16.h>
#include <math.h>
#include <stdint.h>

// Problem constants (fixed by reference setup_inputs)
#define BATCH   2
#define NSEQ    2048
#define DMODEL  1024
#define NHEADS  16
#define DHEAD   64
#define INNER   (NHEADS * DHEAD)       // 1024
#define QKV_N   (3 * INNER)            // 3072
#define WIN     16
#define ATT_SCALE 0.125f
#define MTOT    (BATCH * NSEQ)         // 4096

// ---------------------------------------------------------------------------
// Scratch (device globals: allocation-free rule)
// ---------------------------------------------------------------------------
__device__ float g_qkv[MTOT * QKV_N];                   // [4096, 3072]
__device__ __half g_a_hi[MTOT * DMODEL];                // act fp16 (x, then attn out)
__device__ __half g_wq_hi[QKV_N * DMODEL];              // W_qkv^T fp16 [3072,1024]
__device__ __half g_wo_hi[DMODEL * INNER];              // W_out^T fp16 [1024,1024]

// ---------------------------------------------------------------------------
// PTX helpers (no arch-feature-suffixed instructions: plain compute_103 OK)
// ---------------------------------------------------------------------------
__device__ __forceinline__ uint32_t smem_u32(const void* p) {
    uint32_t a;
    asm("{ .reg .u64 t; cvta.to.shared.u64 t, %1; cvt.u32.u64 %0, t; }"
        : "=r"(a) : "l"(p));
    return a;
}
__device__ __forceinline__ void cp_async16(uint32_t saddr, const void* gaddr) {
    asm volatile("cp.async.cg.shared.global [%0], [%1], 16;"
                 :: "r"(saddr), "l"(gaddr) : "memory");
}
#define CP_COMMIT() asm volatile("cp.async.commit_group;" ::: "memory")
#define CP_WAIT(n)  asm volatile("cp.async.wait_group %0;" :: "n"(n) : "memory")

__device__ __forceinline__ void ldm_x4(uint32_t* r, uint32_t addr) {
    asm volatile("ldmatrix.sync.aligned.m8n8.x4.shared.b16 {%0,%1,%2,%3}, [%4];"
                 : "=r"(r[0]), "=r"(r[1]), "=r"(r[2]), "=r"(r[3]) : "r"(addr));
}
__device__ __forceinline__ void mma_f16(float* d, const uint32_t* a,
                                        const uint32_t* b) {
    asm volatile(
        "mma.sync.aligned.m16n8k16.row.col.f32.f16.f16.f32 "
        "{%0,%1,%2,%3}, {%4,%5,%6,%7}, {%8,%9}, {%0,%1,%2,%3};"
        : "+f"(d[0]), "+f"(d[1]), "+f"(d[2]), "+f"(d[3])
        : "r"(a[0]), "r"(a[1]), "r"(a[2]), "r"(a[3]), "r"(b[0]), "r"(b[1]));
}

// XOR-swizzled smem layout: 64B rows, 4x16B chunks, chunk ^= (row>>1)&3.
// Conflict-free for BOTH cp.async 16B stores and ldmatrix 8-row phases.
__device__ __forceinline__ uint32_t swz(int row, int chunk) {
    return (uint32_t)(row * 64 + ((chunk ^ ((row >> 1) & 3)) << 4));
}

// ---------------------------------------------------------------------------
// Plain fp16 tensor-core GEMM (mma.sync), single K pass:
//   C[M,N] = A@B^T  (+ bias)
// A fp16 [M,K] row-major; B fp16 [N,K] row-major (weights pre-transposed).
// CTA 128x128, BK=32, 8 warps (2M x 4N, warp tile 64x32), swizzled smem,
// 5-stage cp.async, lookahead 4; per stage: CP_WAIT -> barrier -> issue.
// (Round-14 configuration: measured 85.6us @ M=4096,N=3072,K=1024.)
// Requires M%128==0, N%128==0, K%32==0, K>=128.
// ---------------------------------------------------------------------------
#define TILE_B  (128 * 64)              // 8192 B per operand tile (64B rows)
#define STAGE_B (2 * TILE_B)            // A + B = 16384 B
#define NSTAGE  5
#define GSM_BYTES (NSTAGE * STAGE_B)    // 81920

__global__ __launch_bounds__(256, 2)
void gemm_fp16(const __half* __restrict__ A,
               const __half* __restrict__ B,
               const float* __restrict__ bias,
               float* __restrict__ C,
               int M, int N, int K)
{
    constexpr int L = NSTAGE - 1;       // lookahead groups (4)

    extern __shared__ char smem[];
    const uint32_t sbase = smem_u32(smem);

    const int tid    = threadIdx.x;
    const int wid    = tid >> 5;
    const int lane   = tid & 31;
    const int warp_m = wid >> 2;        // 0..1
    const int warp_n = wid & 3;         // 0..3
    const int bm     = blockIdx.y * 128;
    const int bn     = blockIdx.x * 128;

    const int T = K >> 5;               // BK=32 k-tiles

    const int ld_row0 = tid >> 2;              // 0..63
    const int ld_ch   = tid & 3;               // 16B chunk 0..3
    const int a_row_l = (lane & 15);
    const int a_ch_l  = lane >> 4;             // 0..1
    const int b_row_l = ((lane >> 4) << 3) + (lane & 7);
    const int b_ch_l  = (lane >> 3) & 1;

    float acc[4][4][4];
    #pragma unroll
    for (int i = 0; i < 4; i++)
        #pragma unroll
        for (int j = 0; j < 4; j++)
            #pragma unroll
            for (int q = 0; q < 4; q++) acc[i][j][q] = 0.f;

    auto issue = [&](int s) {
        const int kc = s * 32;
        const uint32_t st = sbase + (s % NSTAGE) * STAGE_B;
        #pragma unroll
        for (int i = 0; i < 2; i++) {
            const int row = ld_row0 + i * 64;
            const size_t ga = (size_t)(bm + row) * K + kc + ld_ch * 8;
            const size_t gb = (size_t)(bn + row) * K + kc + ld_ch * 8;
            const uint32_t so = swz(row, ld_ch);
            cp_async16(st + so,          A + ga);
            cp_async16(st + TILE_B + so, B + gb);
        }
        CP_COMMIT();
    };

    #pragma unroll
    for (int i = 0; i < L; i++) issue(i);      // K >= 128 => T >= L

    for (int s = 0; s < T; ++s) {
        // 1) Complete own group s, keeping up to L-1 groups in flight
        if (s + 3 < T)      { CP_WAIT(3); }
        else if (s + 2 < T) { CP_WAIT(2); }
        else if (s + 1 < T) { CP_WAIT(1); }
        else                { CP_WAIT(0); }
        // 2) Publish group s across all threads
        __syncthreads();
        // 3) Refill buffer (s-1)%NSTAGE (fully consumed before this barrier)
        if (s + L < T) issue(s + L);

        const uint32_t stA = sbase + (s % NSTAGE) * STAGE_B;
        const uint32_t stB = stA + TILE_B;

        #pragma unroll
        for (int kk = 0; kk < 2; ++kk) {
            uint32_t bf[2][4];
            #pragma unroll
            for (int nt = 0; nt < 2; ++nt) {
                const int row = warp_n * 32 + nt * 16 + b_row_l;
                ldm_x4(bf[nt], stB + swz(row, kk * 2 + b_ch_l));
            }
            #pragma unroll
            for (int mi = 0; mi < 4; ++mi) {
                uint32_t ah[4];
                const int row = warp_m * 64 + mi * 16 + a_row_l;
                ldm_x4(ah, stA + swz(row, kk * 2 + a_ch_l));
                mma_f16(acc[mi][0], ah, &bf[0][0]);
                mma_f16(acc[mi][1], ah, &bf[0][2]);
                mma_f16(acc[mi][2], ah, &bf[1][0]);
                mma_f16(acc[mi][3], ah, &bf[1][2]);
            }
        }
    }

    // Epilogue
    const int tg = lane >> 2;
    const int tc = (lane & 3) * 2;
    #pragma unroll
    for (int mi = 0; mi < 4; ++mi) {
        const int r0 = bm + warp_m * 64 + mi * 16 + tg;
        #pragma unroll
        for (int ni = 0; ni < 4; ++ni) {
            const int c0 = bn + warp_n * 32 + ni * 8 + tc;
            float2 v0 = make_float2(acc[mi][ni][0], acc[mi][ni][1]);
            float2 v1 = make_float2(acc[mi][ni][2], acc[mi][ni][3]);
            if (bias) {
                const float bx = bias[c0], by = bias[c0 + 1];
                v0.x += bx; v0.y += by;
                v1.x += bx; v1.y += by;
            }
            *(float2*)(C + (size_t)r0 * N + c0)       = v0;
            *(float2*)(C + (size_t)(r0 + 8) * N + c0) = v1;
        }
    }
}

// ---------------------------------------------------------------------------
// fp32 -> fp16 (row-major, elementwise)
// ---------------------------------------------------------------------------
__global__ void split_hi_kernel(const float4* __restrict__ in,
                                uint2* __restrict__ hi, int n4)
{
    int i = blockIdx.x * blockDim.x + threadIdx.x;
    if (i >= n4) return;
    float4 v = in[i];
    union { __half h[4]; uint2 u; } H;
    #pragma unroll
    for (int j = 0; j < 4; ++j) H.h[j] = __float2half((&v.x)[j]);
    hi[i] = H.u;
}

// ---------------------------------------------------------------------------
// Transpose + convert: in fp32 [K,N] -> fp16 [N,K]
// ---------------------------------------------------------------------------
__global__ void tconv_kernel(const float* __restrict__ in,
                             __half* __restrict__ hi, int K, int N)
{
    __shared__ float t[32][33];
    const int tx = threadIdx.x & 31, ty = threadIdx.x >> 5;
    const int n0 = blockIdx.x * 32, k0 = blockIdx.y * 32;
    #pragma unroll
    for (int i = 0; i < 4; ++i)
        t[ty + i * 8][tx] = in[(size_t)(k0 + ty + i * 8) * N + n0 + tx];
    __syncthreads();
    #pragma unroll
    for (int i = 0; i < 4; ++i) {
        float v = t[tx][ty + i * 8];
        hi[(size_t)(n0 + ty + i * 8) * K + k0 + tx] = __float2half(v);
    }
}

// ---------------------------------------------------------------------------
// Windowed attention (top-k & padding masks are provable no-ops).
// Lane-per-key float4 scoring + lane-per-dim AV. Emits fp16 output.
// K/V rows padded to 68 floats: float4-aligned, conflict-free lane-per-key.
// ---------------------------------------------------------------------------
__global__ __launch_bounds__(256)
void attn_window_kernel(const float* __restrict__ qkv,
                        __half* __restrict__ ohi)
{
    __shared__ float qs[32][64];
    __shared__ float ks[64][68];
    __shared__ float vs[64][68];
    __shared__ float ps[8][4][34];

    const int qtile = blockIdx.x * 32;
    const int h     = blockIdx.y;
    const int bb    = blockIdx.z;
    const int tid   = threadIdx.x;

    const int kstart = qtile - WIN;
    const long base  = (long)bb * NSEQ * QKV_N;
    const int hoff   = h * DHEAD;

    #pragma unroll
    for (int idx = tid; idx < 32 * 16; idx += 256) {
        int r = idx >> 4, c = (idx & 15) << 2;
        *(float4*)(&qs[r][c]) =
            *(const float4*)(qkv + base + (long)(qtile + r) * QKV_N + hoff + c);
    }
    #pragma unroll
    for (int idx = tid; idx < 64 * 16; idx += 256) {
        int r = idx >> 4, c = (idx & 15) << 2;
        int jg = kstart + r;
        float4 kv = make_float4(0.f, 0.f, 0.f, 0.f);
        float4 vv = make_float4(0.f, 0.f, 0.f, 0.f);
        if (jg >= 0 && jg < NSEQ) {
            const float* rowp = qkv + base + (long)jg * QKV_N + hoff;
            kv = *(const float4*)(rowp + INNER + c);
            vv = *(const float4*)(rowp + 2 * INNER + c);
        }
        *(float4*)(&ks[r][c]) = kv;
        *(float4*)(&vs[r][c]) = vv;
    }
    __syncthreads();

    const int warp = tid >> 5;
    const int lane = tid & 31;

    #pragma unroll
    for (int q4 = 0; q4 < 4; ++q4) {
        const int qq = warp * 4 + q4;
        const int i  = qtile + qq;
        const int j0 = max(0, i - WIN);
        const int j1 = min(NSEQ - 1, i + WIN);
        const int W  = j1 - j0 + 1;
        const int rb  = j0 - kstart;
        const int jj  = rb + lane;
        const int jj2 = rb + 32;
        const bool v1 = (lane < W);
        const bool v2 = (W == 33);

        // float4 dot products (lane-per-key; q read is broadcast)
        float acc1 = 0.f, acc2 = 0.f;
        const float4* k1p = (const float4*)ks[jj];
        const float4* k2p = (const float4*)ks[jj2];
        const float4* qp  = (const float4*)qs[qq];
        #pragma unroll
        for (int d4 = 0; d4 < 16; ++d4) {
            const float4 qv = qp[d4];
            const float4 k1 = k1p[d4];
            const float4 k2 = k2p[d4];
            acc1 = fmaf(qv.x, k1.x, acc1); acc1 = fmaf(qv.y, k1.y, acc1);
            acc1 = fmaf(qv.z, k1.z, acc1); acc1 = fmaf(qv.w, k1.w, acc1);
            acc2 = fmaf(qv.x, k2.x, acc2); acc2 = fmaf(qv.y, k2.y, acc2);
            acc2 = fmaf(qv.z, k2.z, acc2); acc2 = fmaf(qv.w, k2.w, acc2);
        }
        float s1 = v1 ? acc1 * ATT_SCALE : -INFINITY;
        const float s2 = v2 ? acc2 * ATT_SCALE : -INFINITY;

        float m = s1;
        m = fmaxf(m, __shfl_xor_sync(0xffffffffu, m, 16));
        m = fmaxf(m, __shfl_xor_sync(0xffffffffu, m, 8));
        m = fmaxf(m, __shfl_xor_sync(0xffffffffu, m, 4));
        m = fmaxf(m, __shfl_xor_sync(0xffffffffu, m, 2));
        m = fmaxf(m, __shfl_xor_sync(0xffffffffu, m, 1));
        m = fmaxf(m, s2);

        const float e1 = __expf(s1 - m);
        const float e2 = __expf(s2 - m);
        float l = e1;
        l += __shfl_xor_sync(0xffffffffu, l, 16);
        l += __shfl_xor_sync(0xffffffffu, l, 8);
        l += __shfl_xor_sync(0xffffffffu, l, 4);
        l += __shfl_xor_sync(0xffffffffu, l, 2);
        l += __shfl_xor_sync(0xffffffffu, l, 1);
        l += e2;

        ps[warp][q4][lane] = e1;
        if (lane == 0) ps[warp][q4][32] = e2;
        __syncwarp();

        float a0 = 0.f, a1 = 0.f;
        #pragma unroll
        for (int j = 0; j < 33; ++j) {
            const float p = ps[warp][q4][j];
            a0 = fmaf(p, vs[rb + j][lane],      a0);
            a1 = fmaf(p, vs[rb + j][lane + 32], a1);
        }
        const float inv = 1.f / l;

        const long orow = ((long)(bb * NSEQ + i)) * INNER + hoff;
        ohi[orow + lane]      = __float2half(a0 * inv);
        ohi[orow + lane + 32] = __float2half(a1 * inv);
        __syncwarp();
    }
}

// ---------------------------------------------------------------------------
// kernel_launch
// ---------------------------------------------------------------------------
extern "C" void kernel_launch(void* const* d_in, const int* in_sizes, int n_in,
                              void* d_out, int out_size)
{
    const float* x    = (const float*)d_in[0];
    const float* Wqkv = (const float*)d_in[1];
    const float* Wout = (const float*)d_in[2];
    const float* bout = (const float*)d_in[3];
    float* out = (float*)d_out;

    float* qkv;
    __half *ahi, *wqh, *woh;
    cudaGetSymbolAddress((void**)&qkv, g_qkv);
    cudaGetSymbolAddress((void**)&ahi, g_a_hi);
    cudaGetSymbolAddress((void**)&wqh, g_wq_hi);
    cudaGetSymbolAddress((void**)&woh, g_wo_hi);

    static bool attr_set = false;
    if (!attr_set) {
        cudaFuncSetAttribute(gemm_fp16,
                             cudaFuncAttributeMaxDynamicSharedMemorySize, GSM_BYTES);
        attr_set = true;
    }

    // 1) conversions (x and weights, fp16)
    {
        int n4 = MTOT * DMODEL / 4;
        split_hi_kernel<<<(n4 + 255) / 256, 256>>>((const float4*)x,
                                                   (uint2*)ahi, n4);
        dim3 gq(QKV_N / 32, DMODEL / 32);
        tconv_kernel<<<gq, 256>>>(Wqkv, wqh, DMODEL, QKV_N);
        dim3 go(DMODEL / 32, INNER / 32);
        tconv_kernel<<<go, 256>>>(Wout, woh, INNER, DMODEL);
    }

    // 2) qkv = x @ W_qkv  (fp16, R14 config)
    {
        dim3 grid(QKV_N / 128, MTOT / 128);
        gemm_fp16<<<grid, 256, GSM_BYTES>>>(ahi, wqh, nullptr, qkv,
                                            MTOT, QKV_N, DMODEL);
    }

    // 3) attention -> fp16 output into ahi (float4 version)
    {
        dim3 grid(NSEQ / 32, NHEADS, BATCH);
        attn_window_kernel<<<grid, 256>>>(qkv, ahi);
    }

    // 4) out = att @ W_out + b_out  (fp16, 256 CTAs = single wave)
    {
        dim3 grid(DMODEL / 128, MTOT / 128);
        gemm_fp16<<<grid, 256, GSM_BYTES>>>(ahi, woh, bout, out,
                                            MTOT, DMODEL, INNER);
    }
}